// round 1
// baseline (speedup 1.0000x reference)
#include <cuda_runtime.h>

#define Bb   256
#define Nn   256
#define DIN  128
#define Hh   4
#define DHd  32
#define HID  128   // H*DH
#define NEG  0.2f
#define LNEPS 1e-5f
#define PAD  33

// ---------------- scratch (device globals; no allocation allowed) ----------
__device__ float g_h[(size_t)Bb * Nn * HID];     // x @ W1
__device__ float g_out1[(size_t)Bb * Nn * HID];  // layer-1 attention output + b1
__device__ float g_asrc[Bb * Hh * Nn];           // v_j per (b,h)
__device__ float g_adst[Bb * Hh * Nn];           // u_i per (b,h)
__device__ float g_h2[Bb * Nn];                  // LN(h1) @ W2 (scalar per node)

// ---------------- kernel 1: h = x @ W1  (per-batch 256x128 @ 128x128) ------
__global__ void __launch_bounds__(256) gemm1_kernel(const float* __restrict__ x,
                                                    const float* __restrict__ W) {
    __shared__ float As[16][68];   // As[k][row], padded
    __shared__ float Bs[16][132];  // Bs[k][col], padded
    int b = blockIdx.y;
    int rowBase = blockIdx.x * 64;
    const float* xb = x + ((size_t)(b * Nn + rowBase)) * DIN;
    int tid = threadIdx.x;
    int tx = tid & 15, ty = tid >> 4;

    float acc[4][8];
#pragma unroll
    for (int r = 0; r < 4; r++)
#pragma unroll
        for (int c = 0; c < 8; c++) acc[r][c] = 0.f;

    int arow = tid >> 2, akcol = (tid & 3) << 2;   // A: 64 rows x 16 k
    int brow = tid >> 4, bcol = (tid & 15) << 3;   // B: 16 k x 128 cols

    for (int kk = 0; kk < DIN; kk += 16) {
        float4 av = *(const float4*)(xb + arow * DIN + kk + akcol);
        As[akcol + 0][arow] = av.x;
        As[akcol + 1][arow] = av.y;
        As[akcol + 2][arow] = av.z;
        As[akcol + 3][arow] = av.w;
        const float* wp = W + (size_t)(kk + brow) * HID + bcol;
        float4 w0 = *(const float4*)wp;
        float4 w1 = *(const float4*)(wp + 4);
        *(float4*)&Bs[brow][bcol]     = w0;
        *(float4*)&Bs[brow][bcol + 4] = w1;
        __syncthreads();
#pragma unroll
        for (int k = 0; k < 16; k++) {
            float4 a  = *(const float4*)&As[k][ty * 4];
            float4 b0 = *(const float4*)&Bs[k][tx * 8];
            float4 b1 = *(const float4*)&Bs[k][tx * 8 + 4];
            float ar[4] = {a.x, a.y, a.z, a.w};
            float br[8] = {b0.x, b0.y, b0.z, b0.w, b1.x, b1.y, b1.z, b1.w};
#pragma unroll
            for (int r = 0; r < 4; r++)
#pragma unroll
                for (int c = 0; c < 8; c++) acc[r][c] = fmaf(ar[r], br[c], acc[r][c]);
        }
        __syncthreads();
    }
    float* hb = g_h + ((size_t)(b * Nn + rowBase)) * HID;
#pragma unroll
    for (int r = 0; r < 4; r++) {
        float4 v0 = make_float4(acc[r][0], acc[r][1], acc[r][2], acc[r][3]);
        float4 v1 = make_float4(acc[r][4], acc[r][5], acc[r][6], acc[r][7]);
        *(float4*)(hb + (size_t)(ty * 4 + r) * HID + tx * 8)     = v0;
        *(float4*)(hb + (size_t)(ty * 4 + r) * HID + tx * 8 + 4) = v1;
    }
}

// ---------------- kernel 2: a_src / a_dst per (b, n, head) -----------------
__global__ void __launch_bounds__(256) attprep_kernel(const float* __restrict__ att_src,
                                                      const float* __restrict__ att_dst) {
    int warp = threadIdx.x >> 5, lane = threadIdx.x & 31;
    int node = blockIdx.x * 8 + warp;  // < B*N
    const float* hp = g_h + (size_t)node * HID + lane * 4;
    float4 v = *(const float4*)hp;
    int c = lane * 4;
    float4 as = *(const float4*)(att_src + c);
    float4 ad = *(const float4*)(att_dst + c);
    float ps = v.x * as.x + v.y * as.y + v.z * as.z + v.w * as.w;
    float pd = v.x * ad.x + v.y * ad.y + v.z * ad.z + v.w * ad.w;
#pragma unroll
    for (int off = 4; off; off >>= 1) {
        ps += __shfl_down_sync(0xffffffffu, ps, off, 8);
        pd += __shfl_down_sync(0xffffffffu, pd, off, 8);
    }
    if ((lane & 7) == 0) {
        int head = lane >> 3;
        int b = node >> 8, n = node & 255;
        g_asrc[(b * Hh + head) * Nn + n] = ps;
        g_adst[(b * Hh + head) * Nn + n] = pd;
    }
}

// ---------------- kernel 3: layer-1 attention via sorted prefix/suffix -----
// For each (b, head):
//   w_ij = exp(lrelu(u_i + v_j)) = e^{u_i} e^{v_j}           if v_j > -u_i
//                                = e^{0.2 u_i} e^{0.2 v_j}   otherwise
// Sort v; then numerator/denominator per i are (suffix of e^v h) and
// (prefix of e^{0.2v} h) at the binary-searched split point. Exact.
__global__ void __launch_bounds__(256) attn1_kernel(const float* __restrict__ b1) {
    extern __shared__ float sm[];
    float* sv   = sm;                   // 256  sorted v
    float* ev1  = sv + 256;             // 256  exp(v_sorted)
    float* ev2  = ev1 + 256;            // 256  exp(0.2 v_sorted)
    float* SufS = ev2 + 256;            // 257  scalar suffix of ev1
    float* PreS = SufS + 257;           // 257  scalar exclusive prefix of ev2
    float* hs   = PreS + 257;           // 256*PAD   h values (unsorted)
    float* SufA = hs + 256 * PAD;       // 257*PAD   vector suffix sums
    float* PreB = SufA + 257 * PAD;     // 257*PAD   vector exclusive prefix sums
    int*   sidx = (int*)(PreB + 257 * PAD); // 256   sorted->original index

    int bh = blockIdx.x;               // b*H + head
    int b = bh >> 2, hd = bh & 3;
    int tid = threadIdx.x;

    // 1) stage raw v (reuse SufA as scratch)
    float v = g_asrc[bh * Nn + tid];
    SufA[tid] = v;
    __syncthreads();

    // 2) rank sort (stable via index tiebreak -> permutation)
    int cnt = 0;
#pragma unroll 8
    for (int j = 0; j < Nn; j++) {
        float w = SufA[j];
        cnt += (w < v) || (w == v && j < tid);
    }
    sv[cnt] = v;
    sidx[cnt] = tid;

    // 3) load h tile [256][32] for this head (coalesced)
    for (int idx = tid; idx < Nn * DHd; idx += 256) {
        int j = idx >> 5, d = idx & 31;
        hs[j * PAD + d] = g_h[((size_t)(b * Nn + j)) * HID + hd * DHd + d];
    }
    __syncthreads();

    // 4) exponentials of sorted v
    ev1[tid] = expf(sv[tid]);
    ev2[tid] = expf(NEG * sv[tid]);
    __syncthreads();

    // 5) scans: warp 0 does the 32 per-dim scans, lanes 32/33 do scalars
    if (tid < 32) {
        int d = tid;
        float acc = 0.f;
        SufA[256 * PAD + d] = 0.f;
        for (int r = 255; r >= 0; r--) {
            acc += ev1[r] * hs[sidx[r] * PAD + d];
            SufA[r * PAD + d] = acc;
        }
        float acc2 = 0.f;
        PreB[d] = 0.f;
        for (int r = 0; r < 256; r++) {
            acc2 += ev2[r] * hs[sidx[r] * PAD + d];
            PreB[(r + 1) * PAD + d] = acc2;
        }
    } else if (tid == 32) {
        float a = 0.f;
        SufS[256] = 0.f;
        for (int r = 255; r >= 0; r--) { a += ev1[r]; SufS[r] = a; }
    } else if (tid == 33) {
        float a = 0.f;
        PreS[0] = 0.f;
        for (int r = 0; r < 256; r++) { a += ev2[r]; PreS[r + 1] = a; }
    }
    __syncthreads();

    // 6) query per destination node i = tid
    float u = g_adst[bh * Nn + tid];
    float t = -u;
    int lo = 0, hi = 256;
    while (lo < hi) {
        int mid = (lo + hi) >> 1;
        if (sv[mid] <= t) lo = mid + 1; else hi = mid;
    }
    int k = lo;  // first sorted index with v > -u  (ties either side: identical weight)
    float e1 = expf(u), e2 = expf(NEG * u);
    float den = e1 * SufS[k] + e2 * PreS[k];
    float inv = 1.f / den;
#pragma unroll
    for (int d = 0; d < DHd; d++) {
        float num = e1 * SufA[k * PAD + d] + e2 * PreB[k * PAD + d];
        hs[tid * PAD + d] = num * inv;   // stage for coalesced write
    }
    __syncthreads();

    // 7) coalesced write + bias b1
    for (int idx = tid; idx < Nn * DHd; idx += 256) {
        int j = idx >> 5, d = idx & 31;
        g_out1[((size_t)(b * Nn + j)) * HID + hd * DHd + d] =
            hs[j * PAD + d] + b1[hd * DHd + d];
    }
}

// ---------------- kernel 4: LayerNorm + (h1n @ W2) fused, warp per node ----
__global__ void __launch_bounds__(256) ln_lin_kernel(const float* __restrict__ gamma,
                                                     const float* __restrict__ beta,
                                                     const float* __restrict__ W2) {
    int warp = threadIdx.x >> 5, lane = threadIdx.x & 31;
    int node = blockIdx.x * 8 + warp;
    const float* p = g_out1 + (size_t)node * HID + lane * 4;
    float4 v = *(const float4*)p;
    float s = v.x + v.y + v.z + v.w;
#pragma unroll
    for (int off = 16; off; off >>= 1) s += __shfl_xor_sync(0xffffffffu, s, off);
    float mu = s * (1.f / 128.f);
    float dx = v.x - mu, dy = v.y - mu, dz = v.z - mu, dw = v.w - mu;
    float q = dx * dx + dy * dy + dz * dz + dw * dw;
#pragma unroll
    for (int off = 16; off; off >>= 1) q += __shfl_xor_sync(0xffffffffu, q, off);
    float rstd = rsqrtf(q * (1.f / 128.f) + LNEPS);
    int c = lane * 4;
    float4 g  = *(const float4*)(gamma + c);
    float4 be = *(const float4*)(beta + c);
    float4 w  = *(const float4*)(W2 + c);
    float y0 = dx * rstd * g.x + be.x;
    float y1 = dy * rstd * g.y + be.y;
    float y2 = dz * rstd * g.z + be.z;
    float y3 = dw * rstd * g.w + be.w;
    float hp = y0 * w.x + y1 * w.y + y2 * w.z + y3 * w.w;
#pragma unroll
    for (int off = 16; off; off >>= 1) hp += __shfl_xor_sync(0xffffffffu, hp, off);
    if (lane == 0) g_h2[node] = hp;
}

// ---------------- kernel 5: layer-2 attention (DOUT=1, scalar values) ------
__global__ void __launch_bounds__(256) attn2_kernel(const float* __restrict__ att_src2,
                                                    const float* __restrict__ att_dst2,
                                                    const float* __restrict__ b2,
                                                    float* __restrict__ out) {
    __shared__ float h2s[256];
    __shared__ float vj[256];
    int b = blockIdx.x, i = threadIdx.x;
    float asrc = att_src2[0], adst = att_dst2[0];
    float h2i = g_h2[b * Nn + i];
    h2s[i] = h2i;
    vj[i] = asrc * h2i;
    __syncthreads();
    float u = adst * h2i;
    float num = 0.f, den = 0.f;
#pragma unroll 4
    for (int j = 0; j < Nn; j++) {
        float e = u + vj[j];
        e = e > 0.f ? e : NEG * e;
        float w = expf(e);
        den += w;
        num = fmaf(w, h2s[j], num);
    }
    float o = num / den + b2[0];
    out[b * Nn + i] = o > 0.f ? o : expm1f(o);
}

// ---------------------------------------------------------------------------
static const int SMEM3_BYTES =
    (int)((256 * 3 + 257 * 2 + 256 * PAD + 2 * 257 * PAD) * sizeof(float) +
          256 * sizeof(int));

extern "C" void kernel_launch(void* const* d_in, const int* in_sizes, int n_in,
                              void* d_out, int out_size) {
    (void)in_sizes; (void)n_in; (void)out_size;
    const float* x        = (const float*)d_in[0];
    // d_in[1] = adj (unused; fully-connected graph)
    const float* W1       = (const float*)d_in[2];
    const float* b1       = (const float*)d_in[3];
    const float* att_src1 = (const float*)d_in[4];
    const float* att_dst1 = (const float*)d_in[5];
    const float* gamma    = (const float*)d_in[6];
    const float* beta     = (const float*)d_in[7];
    const float* W2       = (const float*)d_in[8];
    const float* b2       = (const float*)d_in[9];
    const float* att_src2 = (const float*)d_in[10];
    const float* att_dst2 = (const float*)d_in[11];
    float* out = (float*)d_out;

    // idempotent; needed for 108KB dynamic smem on attn1
    cudaFuncSetAttribute(attn1_kernel,
                         cudaFuncAttributeMaxDynamicSharedMemorySize, SMEM3_BYTES);

    dim3 g1(4, Bb);
    gemm1_kernel<<<g1, 256>>>(x, W1);
    attprep_kernel<<<(Bb * Nn) / 8, 256>>>(att_src1, att_dst1);
    attn1_kernel<<<Bb * Hh, 256, SMEM3_BYTES>>>(b1);
    ln_lin_kernel<<<(Bb * Nn) / 8, 256>>>(gamma, beta, W2);
    attn2_kernel<<<Bb, 256>>>(att_src2, att_dst2, b2, out);
}

// round 3
// speedup vs baseline: 1.3475x; 1.3475x over previous
#include <cuda_runtime.h>
#include <cuda_bf16.h>
#include <cstdint>

#define Bb   256
#define Nn   256
#define DIN  128
#define Hh   4
#define DHd  32
#define HID  128   // H*DH
#define NEG  0.2f
#define LNEPS 1e-5f
#define PAD  33
#define MTOT (Bb*Nn)   // 65536

// smem tile geometry for the MMA gemm
#define KS    136            // padded row length (bf16 elems): 272B row stride
#define TILEB (128*KS*2)     // 34816 bytes per 128x128 bf16 tile image
#define AH_OFF 0
#define AL_OFF TILEB
#define BH_OFF (2*TILEB)
#define BL_OFF (3*TILEB)
#define SMEM_GEMM (4*TILEB)  // 139264 bytes

// ---------------- scratch (device globals; no allocation allowed) ----------
__device__ float g_h[(size_t)MTOT * HID];      // x @ W1 (fp32)
__device__ float g_out1[(size_t)MTOT * HID];   // layer-1 attention output + b1
__device__ float g_asrc[Bb * Hh * Nn];
__device__ float g_adst[Bb * Hh * Nn];
__device__ float g_h2[MTOT];
// W1^T bf16 hi/lo, padded [n][KS] image matching smem layout
__device__ __align__(16) __nv_bfloat16 g_whi[HID * KS];
__device__ __align__(16) __nv_bfloat16 g_wlo[HID * KS];

// ---------------- helpers ---------------------------------------------------
__device__ __forceinline__ uint32_t smem_u32(const void* p) {
    return (uint32_t)__cvta_generic_to_shared(p);
}
#define LDM4(r, a)                                                              \
    asm volatile("ldmatrix.sync.aligned.m8n8.x4.shared.b16 {%0,%1,%2,%3}, [%4];"\
                 : "=r"((r)[0]), "=r"((r)[1]), "=r"((r)[2]), "=r"((r)[3])       \
                 : "r"(a))
#define MMA(d, a, b0, b1)                                                       \
    asm volatile("mma.sync.aligned.m16n8k16.row.col.f32.bf16.bf16.f32 "        \
                 "{%0,%1,%2,%3},{%4,%5,%6,%7},{%8,%9},{%0,%1,%2,%3};"          \
                 : "+f"((d)[0]), "+f"((d)[1]), "+f"((d)[2]), "+f"((d)[3])       \
                 : "r"((a)[0]), "r"((a)[1]), "r"((a)[2]), "r"((a)[3]),          \
                   "r"(b0), "r"(b1))

// ---------------- kernel B: W1^T -> bf16 hi/lo padded image ----------------
__global__ void __launch_bounds__(256) convW_kernel(const float* __restrict__ W1) {
    int g = blockIdx.x * 256 + threadIdx.x;   // 16384 elems
    int n = g >> 7, k = g & 127;
    float v = W1[(size_t)k * HID + n];
    __nv_bfloat16 h = __float2bfloat16(v);
    __nv_bfloat16 l = __float2bfloat16(v - __bfloat162float(h));
    g_whi[n * KS + k] = h;
    g_wlo[n * KS + k] = l;
}

// ---------------- GEMM: h = x @ W1 (bf16 split, mma.sync) + fused attprep --
// CTA: 128 rows x N=128, K=128 fully resident. 8 warps = 2(m) x 4(n).
__global__ void __launch_bounds__(256, 1) gemm_kernel(const float* __restrict__ x,
                                                      const float* __restrict__ att_src,
                                                      const float* __restrict__ att_dst) {
    extern __shared__ __align__(16) uint8_t smem[];
    __nv_bfloat16* sAh = (__nv_bfloat16*)(smem + AH_OFF);
    __nv_bfloat16* sAl = (__nv_bfloat16*)(smem + AL_OFF);
    int tid = threadIdx.x, lane = tid & 31, wid = tid >> 5;
    int warpM = wid >> 2, warpN = wid & 3;

    // W hi/lo: straight copy of the padded images (L2-resident, 512 CTAs share)
    {
        const uint4* wh = (const uint4*)g_whi;
        const uint4* wl = (const uint4*)g_wlo;
        uint4* dh = (uint4*)(smem + BH_OFF);
        uint4* dl = (uint4*)(smem + BL_OFF);
#pragma unroll
        for (int i = 0; i < 9; i++) {
            int idx = tid + i * 256;
            if (idx < TILEB / 16) { dh[idx] = wh[idx]; dl[idx] = wl[idx]; }
        }
    }
    // A: load fp32 tile, split to bf16 hi/lo in-flight
    {
        const float4* xp = (const float4*)(x + (size_t)blockIdx.x * 128 * DIN);
#pragma unroll
        for (int i = 0; i < 16; i++) {
            int idx = tid + i * 256;              // 4096 float4
            float4 v = xp[idx];
            int row = idx >> 5, c4 = (idx & 31) * 4;
            float f[4] = {v.x, v.y, v.z, v.w};
            __nv_bfloat16 h[4], l[4];
#pragma unroll
            for (int j = 0; j < 4; j++) {
                h[j] = __float2bfloat16(f[j]);
                l[j] = __float2bfloat16(f[j] - __bfloat162float(h[j]));
            }
            *(uint2*)&sAh[row * KS + c4] = *(const uint2*)h;
            *(uint2*)&sAl[row * KS + c4] = *(const uint2*)l;
        }
    }
    // att vectors for this thread's 8 columns (head == warpN)
    float asv[8], adv[8];
#pragma unroll
    for (int nt = 0; nt < 4; nt++)
#pragma unroll
        for (int j = 0; j < 2; j++) {
            int c = warpN * DHd + nt * 8 + (lane & 3) * 2 + j;
            asv[nt * 2 + j] = att_src[c];
            adv[nt * 2 + j] = att_dst[c];
        }
    __syncthreads();

    uint32_t sbase = smem_u32(smem);
    uint32_t aAddr = sbase + (uint32_t)(warpM * 64 * 272) +
                     (uint32_t)(((lane & 7) + ((lane >> 3) & 1) * 8) * 272 + (lane >> 4) * 16);
    uint32_t bAddr = sbase + (uint32_t)(warpN * 32 * 272) +
                     (uint32_t)(((lane & 7) + ((lane >> 4) & 1) * 8) * 272 + ((lane >> 3) & 1) * 16);

    float acc[4][4][4];
#pragma unroll
    for (int mt = 0; mt < 4; mt++)
#pragma unroll
        for (int nt = 0; nt < 4; nt++)
#pragma unroll
            for (int q = 0; q < 4; q++) acc[mt][nt][q] = 0.f;

    const uint32_t aSel[3] = {AH_OFF, AH_OFF, AL_OFF};
    const uint32_t bSel[3] = {BH_OFF, BL_OFF, BH_OFF};
#pragma unroll
    for (int t = 0; t < 3; t++) {
        uint32_t aT = aAddr + aSel[t];
        uint32_t bT = bAddr + bSel[t];
#pragma unroll
        for (int kc = 0; kc < 8; kc++) {
            uint32_t af[4][4], bf[2][4];
#pragma unroll
            for (int mt = 0; mt < 4; mt++) LDM4(af[mt], aT + mt * 4352 + kc * 32);
#pragma unroll
            for (int pp = 0; pp < 2; pp++) LDM4(bf[pp], bT + pp * 4352 + kc * 32);
#pragma unroll
            for (int mt = 0; mt < 4; mt++)
#pragma unroll
                for (int nt = 0; nt < 4; nt++)
                    MMA(acc[mt][nt], af[mt], bf[nt >> 1][(nt & 1) * 2],
                        bf[nt >> 1][(nt & 1) * 2 + 1]);
        }
    }

    // epilogue: write h rows + fused att dot-products (head == warpN)
    int mbase = blockIdx.x * 128 + warpM * 64;
#pragma unroll
    for (int mt = 0; mt < 4; mt++)
#pragma unroll
        for (int half = 0; half < 2; half++) {
            int m = mbase + mt * 16 + half * 8 + (lane >> 2);
            float* hrow = g_h + (size_t)m * HID + warpN * DHd;
            float ps = 0.f, pd = 0.f;
#pragma unroll
            for (int nt = 0; nt < 4; nt++) {
                float v0 = acc[mt][nt][half * 2 + 0];
                float v1 = acc[mt][nt][half * 2 + 1];
                *(float2*)(hrow + nt * 8 + (lane & 3) * 2) = make_float2(v0, v1);
                ps = fmaf(v0, asv[nt * 2], fmaf(v1, asv[nt * 2 + 1], ps));
                pd = fmaf(v0, adv[nt * 2], fmaf(v1, adv[nt * 2 + 1], pd));
            }
            ps += __shfl_xor_sync(0xffffffffu, ps, 1);
            ps += __shfl_xor_sync(0xffffffffu, ps, 2);
            pd += __shfl_xor_sync(0xffffffffu, pd, 1);
            pd += __shfl_xor_sync(0xffffffffu, pd, 2);
            if ((lane & 3) == 0) {
                int b = m >> 8, n = m & 255;
                g_asrc[(b * Hh + warpN) * Nn + n] = ps;
                g_adst[(b * Hh + warpN) * Nn + n] = pd;
            }
        }
}

// ---------------- kernel 3: layer-1 attention via sorted prefix/suffix -----
__global__ void __launch_bounds__(256) attn1_kernel(const float* __restrict__ b1) {
    extern __shared__ float sm[];
    float* sv   = sm;
    float* ev1  = sv + 256;
    float* ev2  = ev1 + 256;
    float* SufS = ev2 + 256;
    float* PreS = SufS + 257;
    float* hs   = PreS + 257;
    float* SufA = hs + 256 * PAD;
    float* PreB = SufA + 257 * PAD;
    int*   sidx = (int*)(PreB + 257 * PAD);

    int bh = blockIdx.x;
    int b = bh >> 2, hd = bh & 3;
    int tid = threadIdx.x;

    float v = g_asrc[bh * Nn + tid];
    SufA[tid] = v;
    __syncthreads();

    int cnt = 0;
#pragma unroll 8
    for (int j = 0; j < Nn; j++) {
        float w = SufA[j];
        cnt += (w < v) || (w == v && j < tid);
    }
    sv[cnt] = v;
    sidx[cnt] = tid;

    for (int idx = tid; idx < Nn * DHd; idx += 256) {
        int j = idx >> 5, d = idx & 31;
        hs[j * PAD + d] = g_h[((size_t)(b * Nn + j)) * HID + hd * DHd + d];
    }
    __syncthreads();

    ev1[tid] = expf(sv[tid]);
    ev2[tid] = expf(NEG * sv[tid]);
    __syncthreads();

    if (tid < 32) {
        int d = tid;
        float acc = 0.f;
        SufA[256 * PAD + d] = 0.f;
        for (int r = 255; r >= 0; r--) {
            acc += ev1[r] * hs[sidx[r] * PAD + d];
            SufA[r * PAD + d] = acc;
        }
        float acc2 = 0.f;
        PreB[d] = 0.f;
        for (int r = 0; r < 256; r++) {
            acc2 += ev2[r] * hs[sidx[r] * PAD + d];
            PreB[(r + 1) * PAD + d] = acc2;
        }
    } else if (tid == 32) {
        float a = 0.f;
        SufS[256] = 0.f;
        for (int r = 255; r >= 0; r--) { a += ev1[r]; SufS[r] = a; }
    } else if (tid == 33) {
        float a = 0.f;
        PreS[0] = 0.f;
        for (int r = 0; r < 256; r++) { a += ev2[r]; PreS[r + 1] = a; }
    }
    __syncthreads();

    float u = g_adst[bh * Nn + tid];
    float t = -u;
    int lo = 0, hi = 256;
    while (lo < hi) {
        int mid = (lo + hi) >> 1;
        if (sv[mid] <= t) lo = mid + 1; else hi = mid;
    }
    int k = lo;
    float e1 = expf(u), e2 = expf(NEG * u);
    float den = e1 * SufS[k] + e2 * PreS[k];
    float inv = 1.f / den;
#pragma unroll
    for (int d = 0; d < DHd; d++) {
        float num = e1 * SufA[k * PAD + d] + e2 * PreB[k * PAD + d];
        hs[tid * PAD + d] = num * inv;
    }
    __syncthreads();

    for (int idx = tid; idx < Nn * DHd; idx += 256) {
        int j = idx >> 5, d = idx & 31;
        g_out1[((size_t)(b * Nn + j)) * HID + hd * DHd + d] =
            hs[j * PAD + d] + b1[hd * DHd + d];
    }
}

// ---------------- kernel 4: LayerNorm + (h1n @ W2) fused, warp per node ----
__global__ void __launch_bounds__(256) ln_lin_kernel(const float* __restrict__ gamma,
                                                     const float* __restrict__ beta,
                                                     const float* __restrict__ W2) {
    int warp = threadIdx.x >> 5, lane = threadIdx.x & 31;
    int node = blockIdx.x * 8 + warp;
    const float* p = g_out1 + (size_t)node * HID + lane * 4;
    float4 v = *(const float4*)p;
    float s = v.x + v.y + v.z + v.w;
#pragma unroll
    for (int off = 16; off; off >>= 1) s += __shfl_xor_sync(0xffffffffu, s, off);
    float mu = s * (1.f / 128.f);
    float dx = v.x - mu, dy = v.y - mu, dz = v.z - mu, dw = v.w - mu;
    float q = dx * dx + dy * dy + dz * dz + dw * dw;
#pragma unroll
    for (int off = 16; off; off >>= 1) q += __shfl_xor_sync(0xffffffffu, q, off);
    float rstd = rsqrtf(q * (1.f / 128.f) + LNEPS);
    int c = lane * 4;
    float4 g  = *(const float4*)(gamma + c);
    float4 be = *(const float4*)(beta + c);
    float4 w  = *(const float4*)(W2 + c);
    float y0 = dx * rstd * g.x + be.x;
    float y1 = dy * rstd * g.y + be.y;
    float y2 = dz * rstd * g.z + be.z;
    float y3 = dw * rstd * g.w + be.w;
    float hp = y0 * w.x + y1 * w.y + y2 * w.z + y3 * w.w;
#pragma unroll
    for (int off = 16; off; off >>= 1) hp += __shfl_xor_sync(0xffffffffu, hp, off);
    if (lane == 0) g_h2[node] = hp;
}

// ---------------- kernel 5: layer-2 attention (DOUT=1, scalar values) ------
__global__ void __launch_bounds__(256) attn2_kernel(const float* __restrict__ att_src2,
                                                    const float* __restrict__ att_dst2,
                                                    const float* __restrict__ b2,
                                                    float* __restrict__ out) {
    __shared__ float h2s[256];
    __shared__ float vj[256];
    int b = blockIdx.x, i = threadIdx.x;
    float asrc = att_src2[0], adst = att_dst2[0];
    float h2i = g_h2[b * Nn + i];
    h2s[i] = h2i;
    vj[i] = asrc * h2i;
    __syncthreads();
    float u = adst * h2i;
    float num = 0.f, den = 0.f;
#pragma unroll 4
    for (int j = 0; j < Nn; j++) {
        float e = u + vj[j];
        e = e > 0.f ? e : NEG * e;
        float w = expf(e);
        den += w;
        num = fmaf(w, h2s[j], num);
    }
    float o = num / den + b2[0];
    out[b * Nn + i] = o > 0.f ? o : expm1f(o);
}

// ---------------------------------------------------------------------------
static const int SMEM3_BYTES =
    (int)((256 * 3 + 257 * 2 + 256 * PAD + 2 * 257 * PAD) * sizeof(float) +
          256 * sizeof(int));

extern "C" void kernel_launch(void* const* d_in, const int* in_sizes, int n_in,
                              void* d_out, int out_size) {
    (void)in_sizes; (void)n_in; (void)out_size;
    const float* x        = (const float*)d_in[0];
    // d_in[1] = adj (unused; fully-connected graph)
    const float* W1       = (const float*)d_in[2];
    const float* b1       = (const float*)d_in[3];
    const float* att_src1 = (const float*)d_in[4];
    const float* att_dst1 = (const float*)d_in[5];
    const float* gamma    = (const float*)d_in[6];
    const float* beta     = (const float*)d_in[7];
    const float* W2       = (const float*)d_in[8];
    const float* b2       = (const float*)d_in[9];
    const float* att_src2 = (const float*)d_in[10];
    const float* att_dst2 = (const float*)d_in[11];
    float* out = (float*)d_out;

    cudaFuncSetAttribute(attn1_kernel,
                         cudaFuncAttributeMaxDynamicSharedMemorySize, SMEM3_BYTES);
    cudaFuncSetAttribute(gemm_kernel,
                         cudaFuncAttributeMaxDynamicSharedMemorySize, SMEM_GEMM);

    convW_kernel<<<64, 256>>>(W1);
    gemm_kernel<<<MTOT / 128, 256, SMEM_GEMM>>>(x, att_src1, att_dst1);
    attn1_kernel<<<Bb * Hh, 256, SMEM3_BYTES>>>(b1);
    ln_lin_kernel<<<MTOT / 8, 256>>>(gamma, beta, W2);
    attn2_kernel<<<Bb, 256>>>(att_src2, att_dst2, b2, out);
}

// round 4
// speedup vs baseline: 2.3563x; 1.7486x over previous
#include <cuda_runtime.h>
#include <cuda_bf16.h>
#include <cstdint>

#define Bb   256
#define Nn   256
#define DIN  128
#define Hh   4
#define DHd  32
#define HID  128   // H*DH
#define NEG  0.2f
#define LNEPS 1e-5f
#define PAD  33
#define MTOT (Bb*Nn)   // 65536

// smem tile geometry for the MMA gemm
#define KS    136            // padded row length (bf16 elems): 272B row stride
#define TILEB (128*KS*2)     // 34816 bytes per 128x128 bf16 tile image
#define AH_OFF 0
#define AL_OFF TILEB
#define BH_OFF (2*TILEB)
#define BL_OFF (3*TILEB)
#define SMEM_GEMM (4*TILEB)  // 139264 bytes

// ---------------- scratch (device globals; no allocation allowed) ----------
__device__ float g_h[(size_t)MTOT * HID];      // x @ W1 (fp32)
__device__ float g_asrc[Bb * Hh * Nn];
__device__ float g_adst[Bb * Hh * Nn];
__device__ float4 g_part[Bb * Hh * Nn];        // per (b,head,node): {S1,S2,Sg,-}
__device__ float g_gw[HID];                    // gamma * W2
__device__ float g_cgw, g_cbw;                 // sum(gamma*W2), sum(beta*W2)
// W1^T bf16 hi/lo, padded [n][KS] image matching smem layout
__device__ __align__(16) __nv_bfloat16 g_whi[HID * KS];
__device__ __align__(16) __nv_bfloat16 g_wlo[HID * KS];

// ---------------- helpers ---------------------------------------------------
__device__ __forceinline__ uint32_t smem_u32(const void* p) {
    return (uint32_t)__cvta_generic_to_shared(p);
}
#define LDM4(r, a)                                                              \
    asm volatile("ldmatrix.sync.aligned.m8n8.x4.shared.b16 {%0,%1,%2,%3}, [%4];"\
                 : "=r"((r)[0]), "=r"((r)[1]), "=r"((r)[2]), "=r"((r)[3])       \
                 : "r"(a))
#define MMA(d, a, b0, b1)                                                       \
    asm volatile("mma.sync.aligned.m16n8k16.row.col.f32.bf16.bf16.f32 "        \
                 "{%0,%1,%2,%3},{%4,%5,%6,%7},{%8,%9},{%0,%1,%2,%3};"          \
                 : "+f"((d)[0]), "+f"((d)[1]), "+f"((d)[2]), "+f"((d)[3])       \
                 : "r"((a)[0]), "r"((a)[1]), "r"((a)[2]), "r"((a)[3]),          \
                   "r"(b0), "r"(b1))

// ---------------- kernel B: W1^T -> bf16 hi/lo image + LN/W2 constants -----
__global__ void __launch_bounds__(256) convW_kernel(const float* __restrict__ W1,
                                                    const float* __restrict__ gamma,
                                                    const float* __restrict__ beta,
                                                    const float* __restrict__ W2) {
    if (blockIdx.x < 64) {
        int g = blockIdx.x * 256 + threadIdx.x;   // 16384 elems
        int n = g >> 7, k = g & 127;
        float v = W1[(size_t)k * HID + n];
        __nv_bfloat16 h = __float2bfloat16(v);
        __nv_bfloat16 l = __float2bfloat16(v - __bfloat162float(h));
        g_whi[n * KS + k] = h;
        g_wlo[n * KS + k] = l;
    } else {
        __shared__ float rg[8], rb[8];
        int t = threadIdx.x;
        if (t < HID) {
            float w = W2[t];
            float gw = gamma[t] * w;
            float bw = beta[t] * w;
            g_gw[t] = gw;
#pragma unroll
            for (int off = 16; off; off >>= 1) {
                gw += __shfl_xor_sync(0xffffffffu, gw, off);
                bw += __shfl_xor_sync(0xffffffffu, bw, off);
            }
            if ((t & 31) == 0) { rg[t >> 5] = gw; rb[t >> 5] = bw; }
        }
        __syncthreads();
        if (t == 0) {
            g_cgw = rg[0] + rg[1] + rg[2] + rg[3];
            g_cbw = rb[0] + rb[1] + rb[2] + rb[3];
        }
    }
}

// ---------------- GEMM: h = x @ W1 (bf16 split, mma.sync) + fused attprep --
__global__ void __launch_bounds__(256, 1) gemm_kernel(const float* __restrict__ x,
                                                      const float* __restrict__ att_src,
                                                      const float* __restrict__ att_dst) {
    extern __shared__ __align__(16) uint8_t smem[];
    __nv_bfloat16* sAh = (__nv_bfloat16*)(smem + AH_OFF);
    __nv_bfloat16* sAl = (__nv_bfloat16*)(smem + AL_OFF);
    int tid = threadIdx.x, lane = tid & 31, wid = tid >> 5;
    int warpM = wid >> 2, warpN = wid & 3;

    {
        const uint4* wh = (const uint4*)g_whi;
        const uint4* wl = (const uint4*)g_wlo;
        uint4* dh = (uint4*)(smem + BH_OFF);
        uint4* dl = (uint4*)(smem + BL_OFF);
#pragma unroll
        for (int i = 0; i < 9; i++) {
            int idx = tid + i * 256;
            if (idx < TILEB / 16) { dh[idx] = wh[idx]; dl[idx] = wl[idx]; }
        }
    }
    {
        const float4* xp = (const float4*)(x + (size_t)blockIdx.x * 128 * DIN);
#pragma unroll
        for (int i = 0; i < 16; i++) {
            int idx = tid + i * 256;
            float4 v = xp[idx];
            int row = idx >> 5, c4 = (idx & 31) * 4;
            float f[4] = {v.x, v.y, v.z, v.w};
            __nv_bfloat16 h[4], l[4];
#pragma unroll
            for (int j = 0; j < 4; j++) {
                h[j] = __float2bfloat16(f[j]);
                l[j] = __float2bfloat16(f[j] - __bfloat162float(h[j]));
            }
            *(uint2*)&sAh[row * KS + c4] = *(const uint2*)h;
            *(uint2*)&sAl[row * KS + c4] = *(const uint2*)l;
        }
    }
    float asv[8], adv[8];
#pragma unroll
    for (int nt = 0; nt < 4; nt++)
#pragma unroll
        for (int j = 0; j < 2; j++) {
            int c = warpN * DHd + nt * 8 + (lane & 3) * 2 + j;
            asv[nt * 2 + j] = att_src[c];
            adv[nt * 2 + j] = att_dst[c];
        }
    __syncthreads();

    uint32_t sbase = smem_u32(smem);
    uint32_t aAddr = sbase + (uint32_t)(warpM * 64 * 272) +
                     (uint32_t)(((lane & 7) + ((lane >> 3) & 1) * 8) * 272 + (lane >> 4) * 16);
    uint32_t bAddr = sbase + (uint32_t)(warpN * 32 * 272) +
                     (uint32_t)(((lane & 7) + ((lane >> 4) & 1) * 8) * 272 + ((lane >> 3) & 1) * 16);

    float acc[4][4][4];
#pragma unroll
    for (int mt = 0; mt < 4; mt++)
#pragma unroll
        for (int nt = 0; nt < 4; nt++)
#pragma unroll
            for (int q = 0; q < 4; q++) acc[mt][nt][q] = 0.f;

    const uint32_t aSel[3] = {AH_OFF, AH_OFF, AL_OFF};
    const uint32_t bSel[3] = {BH_OFF, BL_OFF, BH_OFF};
#pragma unroll
    for (int t = 0; t < 3; t++) {
        uint32_t aT = aAddr + aSel[t];
        uint32_t bT = bAddr + bSel[t];
#pragma unroll
        for (int kc = 0; kc < 8; kc++) {
            uint32_t af[4][4], bf[2][4];
#pragma unroll
            for (int mt = 0; mt < 4; mt++) LDM4(af[mt], aT + mt * 4352 + kc * 32);
#pragma unroll
            for (int pp = 0; pp < 2; pp++) LDM4(bf[pp], bT + pp * 4352 + kc * 32);
#pragma unroll
            for (int mt = 0; mt < 4; mt++)
#pragma unroll
                for (int nt = 0; nt < 4; nt++)
                    MMA(acc[mt][nt], af[mt], bf[nt >> 1][(nt & 1) * 2],
                        bf[nt >> 1][(nt & 1) * 2 + 1]);
        }
    }

    int mbase = blockIdx.x * 128 + warpM * 64;
#pragma unroll
    for (int mt = 0; mt < 4; mt++)
#pragma unroll
        for (int half = 0; half < 2; half++) {
            int m = mbase + mt * 16 + half * 8 + (lane >> 2);
            float* hrow = g_h + (size_t)m * HID + warpN * DHd;
            float ps = 0.f, pd = 0.f;
#pragma unroll
            for (int nt = 0; nt < 4; nt++) {
                float v0 = acc[mt][nt][half * 2 + 0];
                float v1 = acc[mt][nt][half * 2 + 1];
                *(float2*)(hrow + nt * 8 + (lane & 3) * 2) = make_float2(v0, v1);
                ps = fmaf(v0, asv[nt * 2], fmaf(v1, asv[nt * 2 + 1], ps));
                pd = fmaf(v0, adv[nt * 2], fmaf(v1, adv[nt * 2 + 1], pd));
            }
            ps += __shfl_xor_sync(0xffffffffu, ps, 1);
            ps += __shfl_xor_sync(0xffffffffu, ps, 2);
            pd += __shfl_xor_sync(0xffffffffu, pd, 1);
            pd += __shfl_xor_sync(0xffffffffu, pd, 2);
            if ((lane & 3) == 0) {
                int b = m >> 8, n = m & 255;
                g_asrc[(b * Hh + warpN) * Nn + n] = ps;
                g_adst[(b * Hh + warpN) * Nn + n] = pd;
            }
        }
}

// ---------------- kernel 3: attn1 + fused LN-partials ----------------------
// Sorted prefix/suffix trick (exact); two-level chunked scans (8 warps x 32);
// emits {S1, S2, Sg} per (b,head,node) instead of materializing out1.
__global__ void __launch_bounds__(256) attn1_kernel(const float* __restrict__ b1) {
    extern __shared__ float sm[];
    float* sv    = sm;                       // 256
    float* ev1   = sv + 256;                 // 256
    float* ev2   = ev1 + 256;                // 256
    float* SufS  = ev2 + 256;                // 257 (chunk-local scalar suffix)
    float* PreS  = SufS + 257;               // 257 (chunk-local scalar excl prefix)
    float* OffS1 = PreS + 257;               // 9
    float* OffS2 = OffS1 + 9;                // 9
    float* cS1   = OffS2 + 9;                // 8
    float* cS2   = cS1 + 8;                  // 8
    float* hs    = cS2 + 8;                  // 256*PAD
    float* SufA  = hs + 256 * PAD;           // 257*PAD (chunk-local)
    float* PreB  = SufA + 257 * PAD;         // 257*PAD (chunk-local)
    float* Off1  = PreB + 257 * PAD;         // 9*PAD
    float* Off2  = Off1 + 9 * PAD;           // 9*PAD
    float* cT1   = Off2 + 9 * PAD;           // 8*PAD
    float* cT2   = cT1 + 8 * PAD;            // 8*PAD
    float* sgw   = cT2 + 8 * PAD;            // 32
    float* sb1h  = sgw + 32;                 // 32
    int*   sidx  = (int*)(sb1h + 32);        // 256

    int bh = blockIdx.x;
    int b = bh >> 2, hd = bh & 3;
    int tid = threadIdx.x, lane = tid & 31, w = tid >> 5;

    float v = g_asrc[bh * Nn + tid];
    SufA[tid] = v;                            // raw-v scratch
    __syncthreads();

    int cnt = 0;
#pragma unroll 8
    for (int j = 0; j < Nn; j++) {
        float ww = SufA[j];
        cnt += (ww < v) || (ww == v && j < tid);
    }
    sv[cnt] = v;
    sidx[cnt] = tid;

    for (int idx = tid; idx < Nn * DHd; idx += 256) {
        int j = idx >> 5, d = idx & 31;
        hs[j * PAD + d] = g_h[((size_t)(b * Nn + j)) * HID + hd * DHd + d];
    }
    if (tid < 32) { sgw[tid] = g_gw[hd * DHd + tid]; sb1h[tid] = b1[hd * DHd + tid]; }
    __syncthreads();

    ev1[tid] = __expf(sv[tid]);
    ev2[tid] = __expf(NEG * sv[tid]);
    __syncthreads();

    // --- chunked scans: warp w owns rows [32w, 32w+32), lane = dim d ---
    {
        int base = w * 32, d = lane;
        float acc = 0.f, accS = 0.f;
#pragma unroll
        for (int i = 31; i >= 0; i--) {
            int r = base + i;
            float e = ev1[r];
            acc = fmaf(e, hs[sidx[r] * PAD + d], acc);
            accS += e;
            SufA[r * PAD + d] = acc;
            if (d == 0) SufS[r] = accS;
        }
        cT1[w * PAD + d] = acc;
        if (d == 0) cS1[w] = accS;
        float acc2 = 0.f, accS2 = 0.f;
#pragma unroll
        for (int i = 0; i < 32; i++) {
            int r = base + i;
            PreB[r * PAD + d] = acc2;
            if (d == 0) PreS[r] = accS2;
            float e = ev2[r];
            acc2 = fmaf(e, hs[sidx[r] * PAD + d], acc2);
            accS2 += e;
        }
        cT2[w * PAD + d] = acc2;
        if (d == 0) cS2[w] = accS2;
    }
    __syncthreads();

    // --- offsets table (9 chunks x 32 dims) + row-256 zeros + scalars ---
    for (int it = tid; it < 9 * 32; it += 256) {
        int c = it >> 5, d = it & 31;
        float s1 = 0.f, s2 = 0.f;
        for (int c2 = c + 1; c2 < 8; c2++) s1 += cT1[c2 * PAD + d];
        for (int c2 = 0; c2 < c && c2 < 8; c2++) s2 += cT2[c2 * PAD + d];
        Off1[c * PAD + d] = s1;
        Off2[c * PAD + d] = s2;
    }
    if (tid < PAD) { SufA[256 * PAD + tid] = 0.f; PreB[256 * PAD + tid] = 0.f; }
    if (tid < 9) {
        float s1 = 0.f, s2 = 0.f;
        for (int c2 = tid + 1; c2 < 8; c2++) s1 += cS1[c2];
        for (int c2 = 0; c2 < tid && c2 < 8; c2++) s2 += cS2[c2];
        OffS1[tid] = s1;
        OffS2[tid] = s2;
    }
    if (tid == 0) { SufS[256] = 0.f; PreS[256] = 0.f; }
    __syncthreads();

    // --- query: node i = tid ---
    float u = g_adst[bh * Nn + tid];
    float t = -u;
    int lo = 0, hi = 256;
    while (lo < hi) {
        int mid = (lo + hi) >> 1;
        if (sv[mid] <= t) lo = mid + 1; else hi = mid;
    }
    int k = lo, c = k >> 5;
    float e1 = __expf(u), e2 = __expf(NEG * u);
    float den = e1 * (SufS[k] + OffS1[c]) + e2 * (PreS[k] + OffS2[c]);
    float inv = 1.f / den;
    float s1 = 0.f, s2 = 0.f, sg = 0.f;
#pragma unroll
    for (int d = 0; d < DHd; d++) {
        float num = e1 * (SufA[k * PAD + d] + Off1[c * PAD + d]) +
                    e2 * (PreB[k * PAD + d] + Off2[c * PAD + d]);
        float o = fmaf(num, inv, sb1h[d]);
        s1 += o;
        s2 = fmaf(o, o, s2);
        sg = fmaf(o, sgw[d], sg);
    }
    g_part[bh * Nn + tid] = make_float4(s1, s2, sg, 0.f);
}

// ---------------- kernel 4: LN-finish + layer-2 attention + ELU ------------
__global__ void __launch_bounds__(256) attn2_kernel(const float* __restrict__ att_src2,
                                                    const float* __restrict__ att_dst2,
                                                    const float* __restrict__ b2,
                                                    float* __restrict__ out) {
    __shared__ float h2s[256];
    __shared__ float vj[256];
    int b = blockIdx.x, i = threadIdx.x;
    float s1 = 0.f, s2 = 0.f, sg = 0.f;
#pragma unroll
    for (int hd = 0; hd < Hh; hd++) {
        float4 p = g_part[(b * Hh + hd) * Nn + i];
        s1 += p.x; s2 += p.y; sg += p.z;
    }
    float mu = s1 * (1.f / 128.f);
    float var = s2 * (1.f / 128.f) - mu * mu;
    float rstd = rsqrtf(var + LNEPS);
    float h2i = rstd * (sg - mu * g_cgw) + g_cbw;

    float asrc = att_src2[0], adst = att_dst2[0];
    h2s[i] = h2i;
    vj[i] = asrc * h2i;
    __syncthreads();
    float u = adst * h2i;
    float num = 0.f, den = 0.f;
#pragma unroll 4
    for (int j = 0; j < Nn; j++) {
        float e = u + vj[j];
        e = e > 0.f ? e : NEG * e;
        float w = __expf(e);
        den += w;
        num = fmaf(w, h2s[j], num);
    }
    float o = num / den + b2[0];
    out[b * Nn + i] = o > 0.f ? o : expm1f(o);
}

// ---------------------------------------------------------------------------
static const int SMEM3_BYTES =
    (int)((256 * 3 + 257 * 2 + 9 * 2 + 8 * 2 + 256 * PAD + 2 * 257 * PAD +
           2 * 9 * PAD + 2 * 8 * PAD + 64) * sizeof(float) + 256 * sizeof(int));

extern "C" void kernel_launch(void* const* d_in, const int* in_sizes, int n_in,
                              void* d_out, int out_size) {
    (void)in_sizes; (void)n_in; (void)out_size;
    const float* x        = (const float*)d_in[0];
    // d_in[1] = adj (unused; fully-connected graph)
    const float* W1       = (const float*)d_in[2];
    const float* b1       = (const float*)d_in[3];
    const float* att_src1 = (const float*)d_in[4];
    const float* att_dst1 = (const float*)d_in[5];
    const float* gamma    = (const float*)d_in[6];
    const float* beta     = (const float*)d_in[7];
    const float* W2       = (const float*)d_in[8];
    const float* b2       = (const float*)d_in[9];
    const float* att_src2 = (const float*)d_in[10];
    const float* att_dst2 = (const float*)d_in[11];
    float* out = (float*)d_out;

    cudaFuncSetAttribute(attn1_kernel,
                         cudaFuncAttributeMaxDynamicSharedMemorySize, SMEM3_BYTES);
    cudaFuncSetAttribute(gemm_kernel,
                         cudaFuncAttributeMaxDynamicSharedMemorySize, SMEM_GEMM);

    convW_kernel<<<65, 256>>>(W1, gamma, beta, W2);
    gemm_kernel<<<MTOT / 128, 256, SMEM_GEMM>>>(x, att_src1, att_dst1);
    attn1_kernel<<<Bb * Hh, 256, SMEM3_BYTES>>>(b1);
    attn2_kernel<<<Bb, 256>>>(att_src2, att_dst2, b2, out);
}